// round 1
// baseline (speedup 1.0000x reference)
#include <cuda_runtime.h>
#include <math.h>

#define HEAD   16
#define HDIM   64
#define NROT   32
#define BATCH  8
#define SEQ    4096
#define NROWS  (BATCH * SEQ * HEAD)   // 524288 rows of 64 floats

// Combined linear map: blended-rotation composition @ r_matrix, columns permuted
// so that col d<32 = original col 2d (x1) and col d>=32 = original col 2(d-32)+1 (x2).
__device__ float g_M[HDIM * HDIM];
// Per-position table: for each s in [0,4096): cos[0..31], sin[0..31]
__device__ float g_tab[SEQ * 64];

// ---------------------------------------------------------------------------
// Setup kernel 1: build the 64x64 combined matrix.
// Each blended step is linear, so apply the reference step arithmetic to the
// identity matrix (thread r owns row r; steps only touch row-local data),
// then multiply by r_matrix with the RoPE even/odd permutation folded in.
// ---------------------------------------------------------------------------
__global__ void build_M_kernel(const float* __restrict__ thetas,
                               const float* __restrict__ theta_scale,
                               const float* __restrict__ r_matrix,
                               const int*   __restrict__ pairs) {
    __shared__ float E[HDIM * HDIM];
    int r = threadIdx.x;  // 64 threads, one per row
    #pragma unroll
    for (int c = 0; c < HDIM; c++) E[r * HDIM + c] = (r == c) ? 1.0f : 0.0f;

    float ts = theta_scale[0];
    for (int st = 0; st < NROT; st++) {
        int i = pairs[2 * st + 0];
        int j = pairs[2 * st + 1];
        float th = thetas[st] * ts;
        float c = cosf(th);
        float s = sinf(th);
        float xi = E[r * HDIM + i];
        float xj = E[r * HDIM + j];
        float gi = xi * c + xj * s;
        float gj = -xi * s + xj * c;
        float ni = (2.0f * gi + xi - 2.0f * gi * c) * (1.0f / 3.0f);
        float nj = (2.0f * gj + xj - 2.0f * gi * s) * (1.0f / 3.0f);
        E[r * HDIM + i] = ni;
        E[r * HDIM + j] = nj;
    }
    // no __syncthreads needed: each thread only ever touched its own row

    for (int d = 0; d < HDIM; d++) {
        int col = (d < 32) ? (2 * d) : (2 * (d - 32) + 1);
        float acc = 0.0f;
        for (int c = 0; c < HDIM; c++)
            acc = fmaf(E[r * HDIM + c], r_matrix[c * HDIM + col], acc);
        g_M[r * HDIM + d] = acc;
    }
}

// ---------------------------------------------------------------------------
// Setup kernel 2: sin/cos table. Match reference semantics: argument is the
// fp32 product pos*inv_freq; compute trig of that fp32 value accurately via
// double-precision range reduction (args go up to ~4096, where fast-math
// __sinf alone would lose ~5e-4).
// ---------------------------------------------------------------------------
__global__ void build_tab_kernel(const float* __restrict__ inv_freq) {
    int idx = blockIdx.x * blockDim.x + threadIdx.x;
    if (idx >= SEQ * 32) return;
    int s = idx >> 5;
    int d = idx & 31;
    float argf = (float)s * inv_freq[d];        // same fp32 rounding as reference
    double a = (double)argf;
    double k = rint(a * 0.15915494309189535);   // 1/(2*pi)
    double rr = a - k * 6.283185307179586;      // |rr| <= pi
    float rf = (float)rr;
    g_tab[s * 64 + d]      = cosf(rf);
    g_tab[s * 64 + 32 + d] = sinf(rf);
}

// ---------------------------------------------------------------------------
// Main kernel: out_row = RoPE_diag( x_row @ M ).
// One thread per 64-float row. M broadcast from shared as packed u64 pairs,
// accumulated with fma.rn.f32x2 (2x FP32 FMA throughput on sm_103a).
// ---------------------------------------------------------------------------
__global__ __launch_bounds__(128, 4)
void rot_main_kernel(const float* __restrict__ x, float* __restrict__ out) {
    __shared__ __align__(16) float sM[HDIM * HDIM];   // 16 KB
    __shared__ __align__(16) float sTab[8 * 64];      // 2 KB: 8 positions for this block
    int tid = threadIdx.x;

    {   // cooperative load of M (4096 floats)
        const float4* src = (const float4*)g_M;
        float4* dst = (float4*)sM;
        #pragma unroll
        for (int i = 0; i < 8; i++) dst[tid + 128 * i] = src[tid + 128 * i];
    }
    {   // this block covers 128 consecutive rows = 8 consecutive s values
        int s0 = (int)(((unsigned)blockIdx.x * 128u) >> 4) & (SEQ - 1);
        ((float4*)sTab)[tid] = ((const float4*)(g_tab + s0 * 64))[tid]; // 128 float4
    }
    __syncthreads();

    size_t row = (size_t)blockIdx.x * 128 + tid;
    const float4* xp = (const float4*)(x + row * 64);

    unsigned mbase;
    asm("{ .reg .u64 t; cvta.to.shared.u64 t, %1; cvt.u32.u64 %0, t; }"
        : "=r"(mbase) : "l"((void*)sM));

    unsigned long long acc[32];   // 32 packed f32x2 accumulators = 64 outputs
    #pragma unroll
    for (int p = 0; p < 32; p++) acc[p] = 0ULL;

    float4 xq = xp[0];
    #pragma unroll 1
    for (int kk = 0; kk < 16; kk++) {
        int nxt = kk + 1; if (nxt > 15) nxt = 15;
        float4 xn = xp[nxt];                  // 1-ahead prefetch
        float xa[4] = {xq.x, xq.y, xq.z, xq.w};
        #pragma unroll
        for (int u = 0; u < 4; u++) {
            unsigned long long xk2;
            asm("mov.b64 %0, {%1, %1};" : "=l"(xk2) : "f"(xa[u]));
            unsigned kaddr = mbase + (unsigned)(kk * 4 + u) * 256u;
            #pragma unroll
            for (int d4 = 0; d4 < 16; d4++) {
                unsigned long long m0, m1;
                asm volatile("ld.shared.v2.u64 {%0, %1}, [%2];"
                             : "=l"(m0), "=l"(m1) : "r"(kaddr + d4 * 16));
                asm("fma.rn.f32x2 %0, %1, %2, %0;"
                    : "+l"(acc[2 * d4])     : "l"(xk2), "l"(m0));
                asm("fma.rn.f32x2 %0, %1, %2, %0;"
                    : "+l"(acc[2 * d4 + 1]) : "l"(xk2), "l"(m1));
            }
        }
        xq = xn;
    }

    // Epilogue: out[d] = y[d]*cos[d] - y[d+32]*sin[d];
    //           out[d+32] = y[d]*sin[d] + y[d+32]*cos[d]
    const float* tb = sTab + (tid >> 4) * 64;   // 16 rows per position
    float* orow = out + row * 64;
    #pragma unroll
    for (int ph = 0; ph < 8; ph++) {
        float y0e, y0o, y1e, y1o, z0e, z0o, z1e, z1o;
        asm("mov.b64 {%0, %1}, %2;" : "=f"(y0e), "=f"(y0o) : "l"(acc[2 * ph]));
        asm("mov.b64 {%0, %1}, %2;" : "=f"(y1e), "=f"(y1o) : "l"(acc[2 * ph + 1]));
        asm("mov.b64 {%0, %1}, %2;" : "=f"(z0e), "=f"(z0o) : "l"(acc[16 + 2 * ph]));
        asm("mov.b64 {%0, %1}, %2;" : "=f"(z1e), "=f"(z1o) : "l"(acc[16 + 2 * ph + 1]));
        float c0 = tb[4 * ph + 0], c1 = tb[4 * ph + 1];
        float c2 = tb[4 * ph + 2], c3 = tb[4 * ph + 3];
        float s0 = tb[32 + 4 * ph + 0], s1 = tb[32 + 4 * ph + 1];
        float s2 = tb[32 + 4 * ph + 2], s3 = tb[32 + 4 * ph + 3];
        float4 lo, hi;
        lo.x = y0e * c0 - z0e * s0;
        lo.y = y0o * c1 - z0o * s1;
        lo.z = y1e * c2 - z1e * s2;
        lo.w = y1o * c3 - z1o * s3;
        hi.x = y0e * s0 + z0e * c0;
        hi.y = y0o * s1 + z0o * c1;
        hi.z = y1e * s2 + z1e * c2;
        hi.w = y1o * s3 + z1o * c3;
        ((float4*)orow)[ph]     = lo;
        ((float4*)orow)[8 + ph] = hi;
    }
}

// ---------------------------------------------------------------------------
extern "C" void kernel_launch(void* const* d_in, const int* in_sizes, int n_in,
                              void* d_out, int out_size) {
    const float* x           = (const float*)d_in[0];
    const float* thetas      = (const float*)d_in[1];
    const float* theta_scale = (const float*)d_in[2];
    const float* r_matrix    = (const float*)d_in[3];
    const float* inv_freq    = (const float*)d_in[4];
    const int*   pairs       = (const int*)d_in[5];
    float* out = (float*)d_out;

    build_M_kernel<<<1, 64>>>(thetas, theta_scale, r_matrix, pairs);
    build_tab_kernel<<<(SEQ * 32 + 255) / 256, 256>>>(inv_freq);
    rot_main_kernel<<<NROWS / 128, 128>>>(x, out);
}

// round 2
// speedup vs baseline: 1.3652x; 1.3652x over previous
#include <cuda_runtime.h>
#include <math.h>

#define HEAD   16
#define HDIM   64
#define NROT   32
#define BATCH  8
#define SEQ    4096
#define NROWS  (BATCH * SEQ * HEAD)   // 524288 rows of 64 floats

// Combined linear map: blended-rotation composition @ r_matrix, columns permuted
// so that col d<32 = original col 2d (x1) and col d>=32 = original col 2(d-32)+1 (x2).
__device__ float g_M[HDIM * HDIM];
// Per-position table: for each s in [0,4096): cos[0..31], sin[0..31]
__device__ float g_tab[SEQ * 64];

// ---------------------------------------------------------------------------
// Combined setup kernel.
// Block 0: build the 64x64 combined matrix M = Blend(I) @ R (with RoPE column
//          permutation folded in). r_matrix staged in shared; matmul spread
//          over 256 threads (16 outputs each) instead of the old 64-thread
//          serial global-load loop that cost 78us.
// Blocks 1..512: sin/cos table (4096 positions x 32 freqs), fp32-arg trig with
//          double range reduction to match jnp fp32 semantics.
// ---------------------------------------------------------------------------
__global__ void setup_kernel(const float* __restrict__ thetas,
                             const float* __restrict__ theta_scale,
                             const float* __restrict__ r_matrix,
                             const float* __restrict__ inv_freq,
                             const int*   __restrict__ pairs) {
    if (blockIdx.x == 0) {
        __shared__ float E[HDIM * HDIM];
        __shared__ float sR[HDIM * HDIM];
        int t = threadIdx.x;  // 256 threads

        #pragma unroll
        for (int i = 0; i < 16; i++) sR[t + 256 * i] = r_matrix[t + 256 * i];

        if (t < HDIM) {
            int r = t;  // this thread owns row r of E through all 32 steps
            float row[HDIM];
            #pragma unroll
            for (int c = 0; c < HDIM; c++) row[c] = (r == c) ? 1.0f : 0.0f;
            float ts = theta_scale[0];
            for (int st = 0; st < NROT; st++) {
                int i = pairs[2 * st + 0];
                int j = pairs[2 * st + 1];
                float th = thetas[st] * ts;
                float c = cosf(th);
                float s = sinf(th);
                float xi = row[i];
                float xj = row[j];
                float gi = xi * c + xj * s;
                float gj = -xi * s + xj * c;
                row[i] = (2.0f * gi + xi - 2.0f * gi * c) * (1.0f / 3.0f);
                row[j] = (2.0f * gj + xj - 2.0f * gi * s) * (1.0f / 3.0f);
            }
            #pragma unroll
            for (int c = 0; c < HDIM; c++) E[r * HDIM + c] = row[c];
        }
        __syncthreads();

        // 256 threads x 16 outputs: thread t -> row r = t/4, d = (t&3) + 4*k
        int r = t >> 2;
        int dl = t & 3;
        #pragma unroll
        for (int k = 0; k < 16; k++) {
            int d = dl + 4 * k;
            int col = (d < 32) ? (2 * d) : (2 * (d - 32) + 1);
            float acc = 0.0f;
            #pragma unroll
            for (int c = 0; c < HDIM; c++)
                acc = fmaf(E[r * HDIM + c], sR[c * HDIM + col], acc);
            g_M[r * HDIM + d] = acc;
        }
    } else {
        int idx = (blockIdx.x - 1) * 256 + threadIdx.x;  // < SEQ*32
        int s = idx >> 5;
        int d = idx & 31;
        float argf = (float)s * inv_freq[d];        // same fp32 rounding as reference
        double a = (double)argf;
        double k = rint(a * 0.15915494309189535);   // 1/(2*pi)
        double rr = a - k * 6.283185307179586;      // |rr| <= pi
        float rf = (float)rr;
        g_tab[s * 64 + d]      = cosf(rf);
        g_tab[s * 64 + 32 + d] = sinf(rf);
    }
}

// ---------------------------------------------------------------------------
// Main kernel: out_row = RoPE_diag( x_row @ M ).
// One thread per 64-float row. M broadcast from shared as packed u64 pairs,
// accumulated with fma.rn.f32x2 (2x FP32 FMA throughput on sm_103a).
// ---------------------------------------------------------------------------
__global__ __launch_bounds__(128, 4)
void rot_main_kernel(const float* __restrict__ x, float* __restrict__ out) {
    __shared__ __align__(16) float sM[HDIM * HDIM];   // 16 KB
    __shared__ __align__(16) float sTab[8 * 64];      // 2 KB: 8 positions for this block
    int tid = threadIdx.x;

    {   // cooperative load of M (4096 floats)
        const float4* src = (const float4*)g_M;
        float4* dst = (float4*)sM;
        #pragma unroll
        for (int i = 0; i < 8; i++) dst[tid + 128 * i] = src[tid + 128 * i];
    }
    {   // this block covers 128 consecutive rows = 8 consecutive s values
        int s0 = (int)(((unsigned)blockIdx.x * 128u) >> 4) & (SEQ - 1);
        ((float4*)sTab)[tid] = ((const float4*)(g_tab + s0 * 64))[tid]; // 128 float4
    }
    __syncthreads();

    size_t row = (size_t)blockIdx.x * 128 + tid;
    const float4* xp = (const float4*)(x + row * 64);

    unsigned mbase;
    asm("{ .reg .u64 t; cvta.to.shared.u64 t, %1; cvt.u32.u64 %0, t; }"
        : "=r"(mbase) : "l"((void*)sM));

    unsigned long long acc[32];   // 32 packed f32x2 accumulators = 64 outputs
    #pragma unroll
    for (int p = 0; p < 32; p++) acc[p] = 0ULL;

    float4 xq = xp[0];
    #pragma unroll 1
    for (int kk = 0; kk < 16; kk++) {
        int nxt = kk + 1; if (nxt > 15) nxt = 15;
        float4 xn = xp[nxt];                  // 1-ahead prefetch
        float xa[4] = {xq.x, xq.y, xq.z, xq.w};
        #pragma unroll
        for (int u = 0; u < 4; u++) {
            unsigned long long xk2;
            asm("mov.b64 %0, {%1, %1};" : "=l"(xk2) : "f"(xa[u]));
            unsigned kaddr = mbase + (unsigned)(kk * 4 + u) * 256u;
            #pragma unroll
            for (int d4 = 0; d4 < 16; d4++) {
                unsigned long long m0, m1;
                asm volatile("ld.shared.v2.u64 {%0, %1}, [%2];"
                             : "=l"(m0), "=l"(m1) : "r"(kaddr + d4 * 16));
                asm("fma.rn.f32x2 %0, %1, %2, %0;"
                    : "+l"(acc[2 * d4])     : "l"(xk2), "l"(m0));
                asm("fma.rn.f32x2 %0, %1, %2, %0;"
                    : "+l"(acc[2 * d4 + 1]) : "l"(xk2), "l"(m1));
            }
        }
        xq = xn;
    }

    // Epilogue: out[d] = y[d]*cos[d] - y[d+32]*sin[d];
    //           out[d+32] = y[d]*sin[d] + y[d+32]*cos[d]
    const float* tb = sTab + (tid >> 4) * 64;   // 16 rows per position
    float* orow = out + row * 64;
    #pragma unroll
    for (int ph = 0; ph < 8; ph++) {
        float y0e, y0o, y1e, y1o, z0e, z0o, z1e, z1o;
        asm("mov.b64 {%0, %1}, %2;" : "=f"(y0e), "=f"(y0o) : "l"(acc[2 * ph]));
        asm("mov.b64 {%0, %1}, %2;" : "=f"(y1e), "=f"(y1o) : "l"(acc[2 * ph + 1]));
        asm("mov.b64 {%0, %1}, %2;" : "=f"(z0e), "=f"(z0o) : "l"(acc[16 + 2 * ph]));
        asm("mov.b64 {%0, %1}, %2;" : "=f"(z1e), "=f"(z1o) : "l"(acc[16 + 2 * ph + 1]));
        float c0 = tb[4 * ph + 0], c1 = tb[4 * ph + 1];
        float c2 = tb[4 * ph + 2], c3 = tb[4 * ph + 3];
        float s0 = tb[32 + 4 * ph + 0], s1 = tb[32 + 4 * ph + 1];
        float s2 = tb[32 + 4 * ph + 2], s3 = tb[32 + 4 * ph + 3];
        float4 lo, hi;
        lo.x = y0e * c0 - z0e * s0;
        lo.y = y0o * c1 - z0o * s1;
        lo.z = y1e * c2 - z1e * s2;
        lo.w = y1o * c3 - z1o * s3;
        hi.x = y0e * s0 + z0e * c0;
        hi.y = y0o * s1 + z0o * c1;
        hi.z = y1e * s2 + z1e * c2;
        hi.w = y1o * s3 + z1o * c3;
        ((float4*)orow)[ph]     = lo;
        ((float4*)orow)[8 + ph] = hi;
    }
}

// ---------------------------------------------------------------------------
extern "C" void kernel_launch(void* const* d_in, const int* in_sizes, int n_in,
                              void* d_out, int out_size) {
    const float* x           = (const float*)d_in[0];
    const float* thetas      = (const float*)d_in[1];
    const float* theta_scale = (const float*)d_in[2];
    const float* r_matrix    = (const float*)d_in[3];
    const float* inv_freq    = (const float*)d_in[4];
    const int*   pairs       = (const int*)d_in[5];
    float* out = (float*)d_out;

    // block 0 builds M; blocks 1..512 build the sin/cos table (512*256 = SEQ*32)
    setup_kernel<<<1 + (SEQ * 32) / 256, 256>>>(thetas, theta_scale, r_matrix,
                                                inv_freq, pairs);
    rot_main_kernel<<<NROWS / 128, 128>>>(x, out);
}

// round 3
// speedup vs baseline: 1.9722x; 1.4446x over previous
#include <cuda_runtime.h>
#include <math.h>

#define HEAD   16
#define HDIM   64
#define NROT   32
#define BATCH  8
#define SEQ    4096
#define NROWS  (BATCH * SEQ * HEAD)   // 524288 rows of 64 floats

// Combined linear map: blended-rotation composition @ r_matrix, columns permuted
// so that col d<32 = original col 2d (x1) and col d>=32 = original col 2(d-32)+1 (x2).
__device__ float g_M[HDIM * HDIM];
// Per-position table: for each s in [0,4096): cos[0..31], sin[0..31]
__device__ float g_tab[SEQ * 64];

// ---------------------------------------------------------------------------
// Combined setup kernel.
// Block 0: build M = Blend(I) @ R (RoPE column permutation folded in).
// Blocks 1..512: sin/cos table. fp32 Cody-Waite range reduction:
//   args < 4096 -> k = rint(a/2pi) <= 652 (10 bits); C1 = 6.28125 (8 mantissa
//   bits) so k*C1 is exact; two-term reduction leaves |err| < 1e-7.
// ---------------------------------------------------------------------------
__global__ void setup_kernel(const float* __restrict__ thetas,
                             const float* __restrict__ theta_scale,
                             const float* __restrict__ r_matrix,
                             const float* __restrict__ inv_freq,
                             const int*   __restrict__ pairs) {
    if (blockIdx.x == 0) {
        __shared__ float E[HDIM * HDIM];
        __shared__ float sR[HDIM * HDIM];
        int t = threadIdx.x;  // 256 threads

        #pragma unroll
        for (int i = 0; i < 16; i++) sR[t + 256 * i] = r_matrix[t + 256 * i];

        if (t < HDIM) {
            int r = t;
            float row[HDIM];
            #pragma unroll
            for (int c = 0; c < HDIM; c++) row[c] = (r == c) ? 1.0f : 0.0f;
            float ts = theta_scale[0];
            for (int st = 0; st < NROT; st++) {
                int i = pairs[2 * st + 0];
                int j = pairs[2 * st + 1];
                float th = thetas[st] * ts;
                float c = cosf(th);
                float s = sinf(th);
                float xi = row[i];
                float xj = row[j];
                float gi = xi * c + xj * s;
                float gj = -xi * s + xj * c;
                row[i] = (2.0f * gi + xi - 2.0f * gi * c) * (1.0f / 3.0f);
                row[j] = (2.0f * gj + xj - 2.0f * gi * s) * (1.0f / 3.0f);
            }
            #pragma unroll
            for (int c = 0; c < HDIM; c++) E[r * HDIM + c] = row[c];
        }
        __syncthreads();

        int r  = t >> 2;
        int dl = t & 3;
        #pragma unroll
        for (int k = 0; k < 16; k++) {
            int d = dl + 4 * k;
            int col = (d < 32) ? (2 * d) : (2 * (d - 32) + 1);
            float acc = 0.0f;
            #pragma unroll
            for (int c = 0; c < HDIM; c++)
                acc = fmaf(E[r * HDIM + c], sR[c * HDIM + col], acc);
            g_M[r * HDIM + d] = acc;
        }
    } else {
        int idx = (blockIdx.x - 1) * 256 + threadIdx.x;  // < SEQ*32
        int s = idx >> 5;
        int d = idx & 31;
        float a = (float)s * inv_freq[d];          // same fp32 rounding as reference
        float k = rintf(a * 0.15915494309189535f); // k <= 652, exact
        // 2*pi = C1 + C2 + C3 (C1 exact in 8 mantissa bits -> k*C1 exact)
        float rr = fmaf(-k, 6.28125f, a);
        rr = fmaf(-k, 1.9353071795e-3f, rr);
        rr = fmaf(-k, 8.908910206762e-10f, rr);
        g_tab[s * 64 + d]      = cosf(rr);
        g_tab[s * 64 + 32 + d] = sinf(rr);
    }
}

// ---------------------------------------------------------------------------
// Main kernel: out = RoPE_diag( x @ M ), register-tiled GEMM.
// Block = 128 rows x 64 cols, 256 threads; thread tile = 4 rows x 8 cols
// (cols {4g..4g+3} and {4g+32..4g+35} so the RoPE pairing is thread-local).
// x staged transposed in shared so the A fragment is one LDS.128; cols packed
// in f32x2 so M loads land directly as u64 operands for fma.rn.f32x2.
// Per k-step: 3 LDS.128 -> 16 FFMA2 (was 8 LDS : 16 FFMA2 in R1/R2 layout).
// ---------------------------------------------------------------------------
__global__ __launch_bounds__(256)
void rot_main_kernel(const float* __restrict__ x, float* __restrict__ out) {
    __shared__ __align__(16) float sM[HDIM * HDIM];   // 16 KB, sM[k*64+d]
    __shared__ __align__(16) float sXT[HDIM * 128];   // 32 KB, sXT[k*128+r]
    int tid = threadIdx.x;

    {   // cooperative load of M (4096 floats, 4 float4 per thread)
        const float4* src = (const float4*)g_M;
        float4* dst = (float4*)sM;
        #pragma unroll
        for (int i = 0; i < 4; i++) dst[tid + 256 * i] = src[tid + 256 * i];
    }
    {   // stage x transposed: thread t -> row r = t/2, k-half h = t%2
        int r = tid >> 1, h = tid & 1;
        const float4* xr = (const float4*)(x + ((size_t)blockIdx.x * 128 + r) * 64 + h * 32);
        #pragma unroll
        for (int q = 0; q < 8; q++) {
            float4 v = xr[q];
            int k = h * 32 + q * 4;
            sXT[(k + 0) * 128 + r] = v.x;
            sXT[(k + 1) * 128 + r] = v.y;
            sXT[(k + 2) * 128 + r] = v.z;
            sXT[(k + 3) * 128 + r] = v.w;
        }
    }
    __syncthreads();

    int g  = tid & 7;          // col group
    int r0 = (tid >> 3) * 4;   // 4 consecutive local rows (same RoPE position)

    unsigned xbase, mlo;
    asm("{ .reg .u64 t; cvta.to.shared.u64 t, %1; cvt.u32.u64 %0, t; }"
        : "=r"(xbase) : "l"((void*)sXT));
    asm("{ .reg .u64 t; cvta.to.shared.u64 t, %1; cvt.u32.u64 %0, t; }"
        : "=r"(mlo) : "l"((void*)sM));
    xbase += (unsigned)r0 * 4;
    mlo   += (unsigned)g * 16;
    unsigned mhi = mlo + 128;

    // acc[r*4+0..1]: cols (4g,4g+1),(4g+2,4g+3); acc[r*4+2..3]: same +32
    unsigned long long acc[16];
    #pragma unroll
    for (int p = 0; p < 16; p++) acc[p] = 0ULL;

    #pragma unroll 4
    for (int k = 0; k < HDIM; k++) {
        float a0, a1, a2, a3;
        asm volatile("ld.shared.v4.f32 {%0, %1, %2, %3}, [%4];"
                     : "=f"(a0), "=f"(a1), "=f"(a2), "=f"(a3)
                     : "r"(xbase + (unsigned)k * 512u));
        unsigned long long m0, m1, m2, m3;
        asm volatile("ld.shared.v2.u64 {%0, %1}, [%2];"
                     : "=l"(m0), "=l"(m1) : "r"(mlo + (unsigned)k * 256u));
        asm volatile("ld.shared.v2.u64 {%0, %1}, [%2];"
                     : "=l"(m2), "=l"(m3) : "r"(mhi + (unsigned)k * 256u));
        float av[4] = {a0, a1, a2, a3};
        #pragma unroll
        for (int r = 0; r < 4; r++) {
            unsigned long long ar;
            asm("mov.b64 %0, {%1, %1};" : "=l"(ar) : "f"(av[r]));
            asm("fma.rn.f32x2 %0, %1, %2, %0;" : "+l"(acc[r * 4 + 0]) : "l"(ar), "l"(m0));
            asm("fma.rn.f32x2 %0, %1, %2, %0;" : "+l"(acc[r * 4 + 1]) : "l"(ar), "l"(m1));
            asm("fma.rn.f32x2 %0, %1, %2, %0;" : "+l"(acc[r * 4 + 2]) : "l"(ar), "l"(m2));
            asm("fma.rn.f32x2 %0, %1, %2, %0;" : "+l"(acc[r * 4 + 3]) : "l"(ar), "l"(m3));
        }
    }

    // Epilogue: out[d] = y[d]*cos - y[d+32]*sin ; out[d+32] = y[d]*sin + y[d+32]*cos
    size_t grow = (size_t)blockIdx.x * 128 + r0;
    int pos = (int)((grow >> 4) & (SEQ - 1));
    const float4* tb = (const float4*)(g_tab + pos * 64);
    float4 cc = tb[g];        // cos[4g..4g+3]
    float4 ss = tb[8 + g];    // sin[4g..4g+3]

    #pragma unroll
    for (int r = 0; r < 4; r++) {
        float y0, y1, y2, y3, z0, z1, z2, z3;
        asm("mov.b64 {%0, %1}, %2;" : "=f"(y0), "=f"(y1) : "l"(acc[r * 4 + 0]));
        asm("mov.b64 {%0, %1}, %2;" : "=f"(y2), "=f"(y3) : "l"(acc[r * 4 + 1]));
        asm("mov.b64 {%0, %1}, %2;" : "=f"(z0), "=f"(z1) : "l"(acc[r * 4 + 2]));
        asm("mov.b64 {%0, %1}, %2;" : "=f"(z2), "=f"(z3) : "l"(acc[r * 4 + 3]));
        float4 lo, hi;
        lo.x = y0 * cc.x - z0 * ss.x;
        lo.y = y1 * cc.y - z1 * ss.y;
        lo.z = y2 * cc.z - z2 * ss.z;
        lo.w = y3 * cc.w - z3 * ss.w;
        hi.x = y0 * ss.x + z0 * cc.x;
        hi.y = y1 * ss.y + z1 * cc.y;
        hi.z = y2 * ss.z + z2 * cc.z;
        hi.w = y3 * ss.w + z3 * cc.w;
        float* orow = out + (grow + r) * 64;
        ((float4*)orow)[g]     = lo;
        ((float4*)orow)[8 + g] = hi;
    }
}

// ---------------------------------------------------------------------------
extern "C" void kernel_launch(void* const* d_in, const int* in_sizes, int n_in,
                              void* d_out, int out_size) {
    const float* x           = (const float*)d_in[0];
    const float* thetas      = (const float*)d_in[1];
    const float* theta_scale = (const float*)d_in[2];
    const float* r_matrix    = (const float*)d_in[3];
    const float* inv_freq    = (const float*)d_in[4];
    const int*   pairs       = (const int*)d_in[5];
    float* out = (float*)d_out;

    setup_kernel<<<1 + (SEQ * 32) / 256, 256>>>(thetas, theta_scale, r_matrix,
                                                inv_freq, pairs);
    rot_main_kernel<<<NROWS / 128, 256>>>(x, out);
}